// round 2
// baseline (speedup 1.0000x reference)
#include <cuda_runtime.h>

// StatefulSynapseNet: x[N,1,28,28] -> layer1(28->32) -> IF -> synapse filter
// -> layer2(32->10) -> IF -> mean over T=28. Warp-per-sample design.

#define T_STEPS 28
#define F_IN    28
#define C1      32
#define C2      10

#define WARPS_PER_BLOCK 4
#define BLOCK_THREADS   (WARPS_PER_BLOCK * 32)
#define GRID_BLOCKS     2048   // 8192 warps -> 8 samples per warp (65536)

#define GS_STRIDE 36           // padded row stride for g[t][o] (16B aligned rows)
#define H2_STRIDE 11           // padded row stride for h2[t][j]

struct __align__(16) WarpSmem {
    float xs[F_IN * T_STEPS];        // raw copy of x[n]: [f*28 + t], 3136 B
    float gs[T_STEPS * GS_STRIDE];   // synapse output g[t][o], 4032 B
    float h2s[T_STEPS * H2_STRIDE];  // layer2 pre-activation h2[t][j], 1232 B
};

// packed f32x2 FMA (Blackwell): d = a*b + c elementwise on two fp32 lanes
static __device__ __forceinline__ double dfma2(double a, double b, double c) {
    unsigned long long r;
    asm("fma.rn.f32x2 %0, %1, %2, %3;"
        : "=l"(r)
        : "l"(__double_as_longlong(a)),
          "l"(__double_as_longlong(b)),
          "l"(__double_as_longlong(c)));
    return __longlong_as_double(r);
}
static __device__ __forceinline__ double pack2(float lo, float hi) {
    return __hiloint2double(__float_as_int(hi), __float_as_int(lo));
}
static __device__ __forceinline__ float lo2(double d) { return __int_as_float(__double2loint(d)); }
static __device__ __forceinline__ float hi2(double d) { return __int_as_float(__double2hiint(d)); }

__global__ void __launch_bounds__(BLOCK_THREADS, 4)
StatefulSynapseNet_19662360281544_kernel(
    const float* __restrict__ x,     // [N, 28, 28]  (t fastest)
    const float* __restrict__ W1,    // [32, 28]
    const float* __restrict__ b1,    // [32]
    const float* __restrict__ w_syn, // scalar
    const float* __restrict__ W2,    // [10, 32]
    const float* __restrict__ b2,    // [10]
    float* __restrict__ out,         // [N, 10]
    int n_total)
{
    __shared__ WarpSmem ws[WARPS_PER_BLOCK];
    __shared__ __align__(16) float w2s[C2 * C1];
    __shared__ float b2s[C2];

    const int tid  = threadIdx.x;
    const int lane = tid & 31;
    const int wid  = tid >> 5;

    // Block-level staging of layer-2 weights
    for (int i = tid; i < C2 * C1; i += BLOCK_THREADS) w2s[i] = W2[i];
    if (tid < C2) b2s[tid] = b2[tid];
    __syncthreads();

    // Per-lane layer-1 row (lane == output neuron o), duplicated into f32x2 pairs
    double w1p[F_IN];
    #pragma unroll
    for (int f = 0; f < F_IN; f++) {
        float w = W1[lane * F_IN + f];
        w1p[f] = pack2(w, w);
    }
    const float b1r = b1[lane];
    const float inv_tau = 1.0f / (1.0f + expf(-w_syn[0]));  // sigmoid(w_syn)

    WarpSmem& S = ws[wid];
    const int gw      = blockIdx.x * WARPS_PER_BLOCK + wid;
    const int n_warps = gridDim.x * WARPS_PER_BLOCK;

    for (int n = gw; n < n_total; n += n_warps) {
        // ---- Stage x[n] (784 floats, coalesced float4) ----
        const float4* xg  = reinterpret_cast<const float4*>(x + (size_t)n * (F_IN * T_STEPS));
        float4*       xs4 = reinterpret_cast<float4*>(S.xs);
        #pragma unroll
        for (int i = 0; i < 7; i++) {
            int idx = lane + i * 32;
            if (idx < 196) xs4[idx] = xg[idx];
        }
        __syncwarp();

        // ---- Phase A+B: layer1 GEMV (f32x2 over t-pairs) fused with IF + synapse scan ----
        float v = 0.0f, g = 0.0f;
        #pragma unroll
        for (int q = 0; q < 7; q++) {           // 4 timesteps per quad
            double accA = 0.0, accB = 0.0;      // (t0,t1) and (t2,t3) accumulators
            #pragma unroll
            for (int f = 0; f < F_IN; f++) {
                const double2 xv = *reinterpret_cast<const double2*>(&S.xs[f * T_STEPS + q * 4]);
                accA = dfma2(xv.x, w1p[f], accA);
                accB = dfma2(xv.y, w1p[f], accB);
            }
            float h[4];
            h[0] = lo2(accA) + b1r;
            h[1] = hi2(accA) + b1r;
            h[2] = lo2(accB) + b1r;
            h[3] = hi2(accB) + b1r;
            #pragma unroll
            for (int r = 0; r < 4; r++) {
                v += h[r];
                float s = (v >= 1.0f) ? 1.0f : 0.0f;   // spike
                v = (v >= 1.0f) ? 0.0f : v;            // hard reset
                // g <- g - g*sigmoid(w) + s   (match reference op order; no FMA contraction)
                g = (g - __fmul_rn(g, inv_tau)) + s;
                S.gs[(q * 4 + r) * GS_STRIDE + lane] = g;
            }
        }
        __syncwarp();

        // ---- Phase C: layer2 for all t in parallel (lane == timestep t) ----
        if (lane < T_STEPS) {
            const int t = lane;
            double gp[16];                      // g row: 32 floats as 16 f32x2
            const double2* gsr = reinterpret_cast<const double2*>(&S.gs[t * GS_STRIDE]);
            #pragma unroll
            for (int k = 0; k < 8; k++) {
                double2 d = gsr[k];
                gp[2 * k]     = d.x;
                gp[2 * k + 1] = d.y;
            }
            #pragma unroll
            for (int j = 0; j < C2; j++) {
                double acc = 0.0;
                const double2* w2r = reinterpret_cast<const double2*>(&w2s[j * C1]);
                #pragma unroll
                for (int k = 0; k < 8; k++) {
                    double2 w = w2r[k];
                    acc = dfma2(gp[2 * k],     w.x, acc);
                    acc = dfma2(gp[2 * k + 1], w.y, acc);
                }
                float h2 = (lo2(acc) + hi2(acc)) + b2s[j];
                S.h2s[t * H2_STRIDE + j] = h2;
            }
        }
        __syncwarp();

        // ---- Phase D: output IF scan + mean (lane == output class j) ----
        if (lane < C2) {
            float v2 = 0.0f, cnt = 0.0f;
            #pragma unroll
            for (int t = 0; t < T_STEPS; t++) {
                v2 += S.h2s[t * H2_STRIDE + lane];
                if (v2 >= 1.0f) { cnt += 1.0f; v2 = 0.0f; }
            }
            out[(size_t)n * C2 + lane] = cnt / 28.0f;
        }
        __syncwarp();   // protect shared buffers before next sample
    }
}

extern "C" void kernel_launch(void* const* d_in, const int* in_sizes, int n_in,
                              void* d_out, int out_size) {
    const float* x     = (const float*)d_in[0];
    const float* W1    = (const float*)d_in[1];
    const float* b1    = (const float*)d_in[2];
    const float* w_syn = (const float*)d_in[3];
    const float* W2    = (const float*)d_in[4];
    const float* b2    = (const float*)d_in[5];
    float* out = (float*)d_out;

    int n_total = in_sizes[0] / (F_IN * T_STEPS);

    StatefulSynapseNet_19662360281544_kernel<<<GRID_BLOCKS, BLOCK_THREADS>>>(
        x, W1, b1, w_syn, W2, b2, out, n_total);
}

// round 10
// speedup vs baseline: 1.0784x; 1.0784x over previous
#include <cuda_runtime.h>
#include <cstdint>

// StatefulSynapseNet: x[N,1,28,28] -> layer1(28->32) -> IF -> synapse filter
// -> layer2(32->10) -> IF -> mean over T=28. Warp-per-sample design with
// double-buffered cp.async input staging.

#define T_STEPS 28
#define F_IN    28
#define C1      32
#define C2      10

#define WARPS_PER_BLOCK 4
#define BLOCK_THREADS   (WARPS_PER_BLOCK * 32)
#define GRID_BLOCKS     2048   // 8192 warps -> 8 samples per warp (65536)

#define GS_STRIDE 36           // padded row stride for g[t][o] (16B aligned rows)
#define H2_STRIDE 11           // padded row stride for h2[t][j]

#define X_FLOATS  (F_IN * T_STEPS)   // 784

struct __align__(16) WarpSmem {
    float xs[2][X_FLOATS];           // double-buffered x[n]: [f*28 + t]
    float gs[T_STEPS * GS_STRIDE];   // synapse output g[t][o]
    float h2s[T_STEPS * H2_STRIDE];  // layer2 pre-activation h2[t][j]
};

// packed f32x2 FMA (Blackwell): d = a*b + c elementwise on two fp32 lanes
static __device__ __forceinline__ double dfma2(double a, double b, double c) {
    unsigned long long r;
    asm("fma.rn.f32x2 %0, %1, %2, %3;"
        : "=l"(r)
        : "l"(__double_as_longlong(a)),
          "l"(__double_as_longlong(b)),
          "l"(__double_as_longlong(c)));
    return __longlong_as_double(r);
}
static __device__ __forceinline__ double pack2(float lo, float hi) {
    return __hiloint2double(__float_as_int(hi), __float_as_int(lo));
}
static __device__ __forceinline__ float lo2(double d) { return __int_as_float(__double2loint(d)); }
static __device__ __forceinline__ float hi2(double d) { return __int_as_float(__double2hiint(d)); }

// 16B async copy global -> shared
static __device__ __forceinline__ void cp16(unsigned int smem_addr, const void* gptr) {
    asm volatile("cp.async.cg.shared.global [%0], [%1], 16;"
                 :: "r"(smem_addr), "l"(gptr));
}
static __device__ __forceinline__ void cp_commit() {
    asm volatile("cp.async.commit_group;");
}
static __device__ __forceinline__ void cp_wait1() {
    asm volatile("cp.async.wait_group 1;");
}

__global__ void __launch_bounds__(BLOCK_THREADS, 4)
StatefulSynapseNet_19662360281544_kernel(
    const float* __restrict__ x,     // [N, 28, 28]  (t fastest)
    const float* __restrict__ W1,    // [32, 28]
    const float* __restrict__ b1,    // [32]
    const float* __restrict__ w_syn, // scalar
    const float* __restrict__ W2,    // [10, 32]
    const float* __restrict__ b2,    // [10]
    float* __restrict__ out,         // [N, 10]
    int n_total)
{
    __shared__ WarpSmem ws[WARPS_PER_BLOCK];
    __shared__ __align__(16) float w2s[C2 * C1];
    __shared__ float b2s[C2];

    const int tid  = threadIdx.x;
    const int lane = tid & 31;
    const int wid  = tid >> 5;

    // Block-level staging of layer-2 weights
    for (int i = tid; i < C2 * C1; i += BLOCK_THREADS) w2s[i] = W2[i];
    if (tid < C2) b2s[tid] = b2[tid];
    __syncthreads();

    // Per-lane layer-1 row (lane == output neuron o), duplicated into f32x2 pairs
    double w1p[F_IN];
    #pragma unroll
    for (int f = 0; f < F_IN; f++) {
        float w = W1[lane * F_IN + f];
        w1p[f] = pack2(w, w);
    }
    const float b1r = b1[lane];
    const float inv_tau = 1.0f / (1.0f + expf(-w_syn[0]));  // sigmoid(w_syn)

    WarpSmem& S = ws[wid];
    const int gw      = blockIdx.x * WARPS_PER_BLOCK + wid;
    const int n_warps = gridDim.x * WARPS_PER_BLOCK;

    // Shared addresses of the two x buffers (32-bit shared-window addrs)
    unsigned int xs_addr[2];
    xs_addr[0] = (unsigned int)__cvta_generic_to_shared(&S.xs[0][0]);
    xs_addr[1] = (unsigned int)__cvta_generic_to_shared(&S.xs[1][0]);

    // ---- Prologue: prefetch first sample into buffer 0 ----
    {
        int n0 = (gw < n_total) ? gw : 0;
        const char* src = (const char*)(x + (size_t)n0 * X_FLOATS);
        if (lane < F_IN) {
            #pragma unroll
            for (int i = 0; i < 7; i++) {
                int idx = i * F_IN + lane;        // 0..195, coalesced across lanes
                cp16(xs_addr[0] + idx * 16, src + idx * 16);
            }
        }
        cp_commit();
    }

    int cur = 0;
    for (int n = gw; n < n_total; n += n_warps) {
        // ---- Prefetch next sample into the other buffer ----
        {
            int nn = n + n_warps;
            if (nn >= n_total) nn = n;            // harmless re-fetch on tail
            const char* src = (const char*)(x + (size_t)nn * X_FLOATS);
            unsigned int dst = xs_addr[cur ^ 1];
            if (lane < F_IN) {
                #pragma unroll
                for (int i = 0; i < 7; i++) {
                    int idx = i * F_IN + lane;
                    cp16(dst + idx * 16, src + idx * 16);
                }
            }
            cp_commit();
        }
        cp_wait1();          // current buffer's group has landed
        __syncwarp();

        const float* xs = S.xs[cur];

        // ---- Phase A+B: layer1 GEMV (f32x2 over t-pairs) fused with IF + synapse scan ----
        float v = 0.0f, g = 0.0f;
        #pragma unroll
        for (int q = 0; q < 7; q++) {           // 4 timesteps per quad
            double accA = 0.0, accB = 0.0;      // (t0,t1) and (t2,t3) accumulators
            #pragma unroll
            for (int f = 0; f < F_IN; f++) {
                const double2 xv = *reinterpret_cast<const double2*>(&xs[f * T_STEPS + q * 4]);
                accA = dfma2(xv.x, w1p[f], accA);
                accB = dfma2(xv.y, w1p[f], accB);
            }
            float h[4];
            h[0] = lo2(accA) + b1r;
            h[1] = hi2(accA) + b1r;
            h[2] = lo2(accB) + b1r;
            h[3] = hi2(accB) + b1r;
            #pragma unroll
            for (int r = 0; r < 4; r++) {
                v += h[r];
                float s = (v >= 1.0f) ? 1.0f : 0.0f;   // spike
                v = (v >= 1.0f) ? 0.0f : v;            // hard reset
                // g <- g - g*sigmoid(w) + s   (match reference op order; no FMA contraction)
                g = (g - __fmul_rn(g, inv_tau)) + s;
                S.gs[(q * 4 + r) * GS_STRIDE + lane] = g;
            }
        }
        __syncwarp();

        // ---- Phase C: layer2 for all t in parallel (lane == timestep t) ----
        if (lane < T_STEPS) {
            const int t = lane;
            double2 gd[8];                      // g row: 32 floats as 8 double2
            const double2* gsr = reinterpret_cast<const double2*>(&S.gs[t * GS_STRIDE]);
            #pragma unroll
            for (int k = 0; k < 8; k++) gd[k] = gsr[k];

            #pragma unroll
            for (int j = 0; j < C2; j++) {
                double acc = 0.0;
                const double2* w2r = reinterpret_cast<const double2*>(&w2s[j * C1]);
                #pragma unroll
                for (int k = 0; k < 8; k++) {
                    double2 w = w2r[k];
                    acc = dfma2(gd[k].x, w.x, acc);
                    acc = dfma2(gd[k].y, w.y, acc);
                }
                float h2 = (lo2(acc) + hi2(acc)) + b2s[j];
                S.h2s[t * H2_STRIDE + j] = h2;
            }
        }
        __syncwarp();

        // ---- Phase D: output IF scan + mean (lane == output class j) ----
        if (lane < C2) {
            float v2 = 0.0f, cnt = 0.0f;
            #pragma unroll
            for (int t = 0; t < T_STEPS; t++) {
                v2 += S.h2s[t * H2_STRIDE + lane];
                if (v2 >= 1.0f) { cnt += 1.0f; v2 = 0.0f; }
            }
            out[(size_t)n * C2 + lane] = cnt * (1.0f / 28.0f);
        }
        __syncwarp();   // protect shared buffers before next sample
        cur ^= 1;
    }
}

extern "C" void kernel_launch(void* const* d_in, const int* in_sizes, int n_in,
                              void* d_out, int out_size) {
    const float* x     = (const float*)d_in[0];
    const float* W1    = (const float*)d_in[1];
    const float* b1    = (const float*)d_in[2];
    const float* w_syn = (const float*)d_in[3];
    const float* W2    = (const float*)d_in[4];
    const float* b2    = (const float*)d_in[5];
    float* out = (float*)d_out;

    int n_total = in_sizes[0] / X_FLOATS;

    StatefulSynapseNet_19662360281544_kernel<<<GRID_BLOCKS, BLOCK_THREADS>>>(
        x, W1, b1, w_syn, W2, b2, out, n_total);
}

// round 12
// speedup vs baseline: 1.0801x; 1.0016x over previous
#include <cuda_runtime.h>
#include <cstdint>

// StatefulSynapseNet: x[N,1,28,28] -> layer1(28->32) -> IF -> synapse filter
// -> layer2(32->10) -> IF -> mean over T=28. Warp-per-sample design with
// double-buffered cp.async input staging.

#define T_STEPS 28
#define F_IN    28
#define C1      32
#define C2      10

#define WARPS_PER_BLOCK 4
#define BLOCK_THREADS   (WARPS_PER_BLOCK * 32)
#define GRID_BLOCKS     2048   // 8192 warps -> 8 samples per warp (65536)

#define GS_STRIDE 36           // padded row stride for g[t][o] (16B aligned rows)
#define H2_STRIDE 11           // padded row stride for h2[t][j]

#define X_FLOATS  (F_IN * T_STEPS)   // 784

struct __align__(16) WarpSmem {
    float xs[2][X_FLOATS];           // double-buffered x[n]: [f*28 + t]
    float gs[T_STEPS * GS_STRIDE];   // synapse output g[t][o]
    float h2s[T_STEPS * H2_STRIDE];  // layer2 pre-activation h2[t][j]
};

// packed f32x2 FMA (Blackwell): d = a*b + c elementwise on two fp32 lanes
static __device__ __forceinline__ double dfma2(double a, double b, double c) {
    unsigned long long r;
    asm("fma.rn.f32x2 %0, %1, %2, %3;"
        : "=l"(r)
        : "l"(__double_as_longlong(a)),
          "l"(__double_as_longlong(b)),
          "l"(__double_as_longlong(c)));
    return __longlong_as_double(r);
}
static __device__ __forceinline__ double pack2(float lo, float hi) {
    return __hiloint2double(__float_as_int(hi), __float_as_int(lo));
}
static __device__ __forceinline__ float lo2(double d) { return __int_as_float(__double2loint(d)); }
static __device__ __forceinline__ float hi2(double d) { return __int_as_float(__double2hiint(d)); }

// 16B async copy global -> shared
static __device__ __forceinline__ void cp16(unsigned int smem_addr, const void* gptr) {
    asm volatile("cp.async.cg.shared.global [%0], [%1], 16;"
                 :: "r"(smem_addr), "l"(gptr));
}
static __device__ __forceinline__ void cp_commit() {
    asm volatile("cp.async.commit_group;");
}
static __device__ __forceinline__ void cp_wait1() {
    asm volatile("cp.async.wait_group 1;");
}

__global__ void __launch_bounds__(BLOCK_THREADS, 4)
StatefulSynapseNet_19662360281544_kernel(
    const float* __restrict__ x,     // [N, 28, 28]  (t fastest)
    const float* __restrict__ W1,    // [32, 28]
    const float* __restrict__ b1,    // [32]
    const float* __restrict__ w_syn, // scalar
    const float* __restrict__ W2,    // [10, 32]
    const float* __restrict__ b2,    // [10]
    float* __restrict__ out,         // [N, 10]
    int n_total)
{
    __shared__ WarpSmem ws[WARPS_PER_BLOCK];
    __shared__ __align__(16) float w2s[C2 * C1];
    __shared__ float b2s[C2];

    const int tid  = threadIdx.x;
    const int lane = tid & 31;
    const int wid  = tid >> 5;

    // Block-level staging of layer-2 weights
    for (int i = tid; i < C2 * C1; i += BLOCK_THREADS) w2s[i] = W2[i];
    if (tid < C2) b2s[tid] = b2[tid];
    __syncthreads();

    // Per-lane layer-1 row (lane == output neuron o), duplicated into f32x2 pairs
    double w1p[F_IN];
    #pragma unroll
    for (int f = 0; f < F_IN; f++) {
        float w = W1[lane * F_IN + f];
        w1p[f] = pack2(w, w);
    }
    const float b1r = b1[lane];
    const float inv_tau = 1.0f / (1.0f + expf(-w_syn[0]));  // sigmoid(w_syn)

    WarpSmem& S = ws[wid];
    const int gw      = blockIdx.x * WARPS_PER_BLOCK + wid;
    const int n_warps = gridDim.x * WARPS_PER_BLOCK;

    // Shared addresses of the two x buffers (32-bit shared-window addrs)
    unsigned int xs_addr[2];
    xs_addr[0] = (unsigned int)__cvta_generic_to_shared(&S.xs[0][0]);
    xs_addr[1] = (unsigned int)__cvta_generic_to_shared(&S.xs[1][0]);

    // ---- Prologue: prefetch first sample into buffer 0 ----
    {
        int n0 = (gw < n_total) ? gw : 0;
        const char* src = (const char*)(x + (size_t)n0 * X_FLOATS);
        if (lane < F_IN) {
            #pragma unroll
            for (int i = 0; i < 7; i++) {
                int idx = i * F_IN + lane;        // 0..195, coalesced across lanes
                cp16(xs_addr[0] + idx * 16, src + idx * 16);
            }
        }
        cp_commit();
    }

    int cur = 0;
    for (int n = gw; n < n_total; n += n_warps) {
        // ---- Prefetch next sample into the other buffer ----
        {
            int nn = n + n_warps;
            if (nn >= n_total) nn = n;            // harmless re-fetch on tail
            const char* src = (const char*)(x + (size_t)nn * X_FLOATS);
            unsigned int dst = xs_addr[cur ^ 1];
            if (lane < F_IN) {
                #pragma unroll
                for (int i = 0; i < 7; i++) {
                    int idx = i * F_IN + lane;
                    cp16(dst + idx * 16, src + idx * 16);
                }
            }
            cp_commit();
        }
        cp_wait1();          // current buffer's group has landed
        __syncwarp();

        const float* xs = S.xs[cur];

        // ---- Phase A+B: layer1 GEMV (f32x2 over t-pairs) fused with IF + synapse scan ----
        float v = 0.0f, g = 0.0f;
        #pragma unroll
        for (int q = 0; q < 7; q++) {           // 4 timesteps per quad
            double accA = 0.0, accB = 0.0;      // (t0,t1) and (t2,t3) accumulators
            #pragma unroll
            for (int f = 0; f < F_IN; f++) {
                const double2 xv = *reinterpret_cast<const double2*>(&xs[f * T_STEPS + q * 4]);
                accA = dfma2(xv.x, w1p[f], accA);
                accB = dfma2(xv.y, w1p[f], accB);
            }
            float h[4];
            h[0] = lo2(accA) + b1r;
            h[1] = hi2(accA) + b1r;
            h[2] = lo2(accB) + b1r;
            h[3] = hi2(accB) + b1r;
            #pragma unroll
            for (int r = 0; r < 4; r++) {
                v += h[r];
                float s = (v >= 1.0f) ? 1.0f : 0.0f;   // spike
                v = (v >= 1.0f) ? 0.0f : v;            // hard reset
                // g <- g - g*sigmoid(w) + s   (match reference op order; no FMA contraction)
                g = (g - __fmul_rn(g, inv_tau)) + s;
                S.gs[(q * 4 + r) * GS_STRIDE + lane] = g;
            }
        }
        __syncwarp();

        // ---- Phase C: layer2 for all t in parallel (lane == timestep t) ----
        if (lane < T_STEPS) {
            const int t = lane;
            double2 gd[8];                      // g row: 32 floats as 8 double2
            const double2* gsr = reinterpret_cast<const double2*>(&S.gs[t * GS_STRIDE]);
            #pragma unroll
            for (int k = 0; k < 8; k++) gd[k] = gsr[k];

            #pragma unroll
            for (int j = 0; j < C2; j++) {
                double acc = 0.0;
                const double2* w2r = reinterpret_cast<const double2*>(&w2s[j * C1]);
                #pragma unroll
                for (int k = 0; k < 8; k++) {
                    double2 w = w2r[k];
                    acc = dfma2(gd[k].x, w.x, acc);
                    acc = dfma2(gd[k].y, w.y, acc);
                }
                float h2 = (lo2(acc) + hi2(acc)) + b2s[j];
                S.h2s[t * H2_STRIDE + j] = h2;
            }
        }
        __syncwarp();

        // ---- Phase D: output IF scan + mean (lane == output class j) ----
        if (lane < C2) {
            float v2 = 0.0f, cnt = 0.0f;
            #pragma unroll
            for (int t = 0; t < T_STEPS; t++) {
                v2 += S.h2s[t * H2_STRIDE + lane];
                if (v2 >= 1.0f) { cnt += 1.0f; v2 = 0.0f; }
            }
            out[(size_t)n * C2 + lane] = cnt * (1.0f / 28.0f);
        }
        __syncwarp();   // protect shared buffers before next sample
        cur ^= 1;
    }
}

extern "C" void kernel_launch(void* const* d_in, const int* in_sizes, int n_in,
                              void* d_out, int out_size) {
    const float* x     = (const float*)d_in[0];
    const float* W1    = (const float*)d_in[1];
    const float* b1    = (const float*)d_in[2];
    const float* w_syn = (const float*)d_in[3];
    const float* W2    = (const float*)d_in[4];
    const float* b2    = (const float*)d_in[5];
    float* out = (float*)d_out;

    int n_total = in_sizes[0] / X_FLOATS;

    StatefulSynapseNet_19662360281544_kernel<<<GRID_BLOCKS, BLOCK_THREADS>>>(
        x, W1, b1, w_syn, W2, b2, out, n_total);
}